// round 16
// baseline (speedup 1.0000x reference)
#include <cuda_runtime.h>
#include <cuda_fp16.h>
#include <math.h>
#include <cstdint>

#define T_  512
#define B_  256
#define D_  512
#define H_  512
#define H2_ (2*H_)
#define H3_ (3*H_)

#define NBLK  128
#define SNTHR 512

typedef unsigned long long ull;

// ===========================================================================
// Global scratch
// ===========================================================================
__device__ float g_gi[(size_t)T_ * B_ * H3_];          // gi = ins @ Wi + bi
__device__ float g_mask[T_ * B_];
__device__ __half g_ah[(size_t)T_ * B_ * D_];          // ins fp16 [m][k]
__device__ __half g_bh[(size_t)H3_ * D_];              // Wi^T fp16 [n][k]
__device__ __half g_hs[(size_t)T_ * B_ * H_];          // h states fp16 (unmasked)
__device__ unsigned g_flag[NBLK * 32];                 // per-tile step flags

// ===========================================================================
// helpers
// ===========================================================================
__device__ __forceinline__ uint32_t smem_u32(const void* p) {
    uint32_t a;
    asm("{ .reg .u64 t; cvta.to.shared.u64 t, %1; cvt.u32.u64 %0, t; }"
        : "=r"(a) : "l"(p));
    return a;
}

#define LDSM4(R, A) \
    asm volatile("ldmatrix.sync.aligned.m8n8.x4.shared.b16 {%0,%1,%2,%3}, [%4];" \
        : "=r"((R)[0]), "=r"((R)[1]), "=r"((R)[2]), "=r"((R)[3]) : "r"(A))
#define LDSM2(R, A) \
    asm volatile("ldmatrix.sync.aligned.m8n8.x2.shared.b16 {%0,%1}, [%2];" \
        : "=r"((R)[0]), "=r"((R)[1]) : "r"(A))

__device__ __forceinline__ void mma4(float* c, const unsigned* a,
                                     unsigned b0, unsigned b1) {
    asm volatile(
        "mma.sync.aligned.m16n8k16.row.col.f32.f16.f16.f32 "
        "{%0,%1,%2,%3}, {%4,%5,%6,%7}, {%8,%9}, {%0,%1,%2,%3};"
        : "+f"(c[0]), "+f"(c[1]), "+f"(c[2]), "+f"(c[3])
        : "r"(a[0]), "r"(a[1]), "r"(a[2]), "r"(a[3]), "r"(b0), "r"(b1));
}

__device__ __forceinline__ ull cvt4h(float4 v) {
    __half2 a = __floats2half2_rn(v.x, v.y);
    __half2 b = __floats2half2_rn(v.z, v.w);
    ull r;
    asm("mov.b64 %0, {%1, %2};" : "=l"(r)
        : "r"(*(unsigned*)&a), "r"(*(unsigned*)&b));
    return r;
}

__device__ __forceinline__ unsigned ld_acq(const unsigned* p) {
    unsigned v;
    asm volatile("ld.acquire.gpu.u32 %0, [%1];" : "=r"(v) : "l"(p) : "memory");
    return v;
}

#define CP_ASYNC16(smem, gptr) \
    asm volatile("cp.async.cg.shared.global [%0], [%1], 16;" \
                 :: "r"(smem), "l"(gptr) : "memory")
#define CP_COMMIT() asm volatile("cp.async.commit_group;" ::: "memory")
#define CP_WAIT0()  asm volatile("cp.async.wait_group 0;" ::: "memory")

// ===========================================================================
// Reset-mask prep + flag reset (every call — graph replay safe)
// ===========================================================================
__global__ void prep_mask_kernel(const void* __restrict__ resets)
{
    const int N = T_ * B_;
    for (int i = threadIdx.x; i < NBLK * 32; i += blockDim.x)
        g_flag[i] = 0;
    const unsigned char* b8 = (const unsigned char*)resets;
    int found = 0;
    for (int i = threadIdx.x; i < N; i += blockDim.x)
        if ((i & 3) && b8[i] == 1) found = 1;
    int is_byte = __syncthreads_or(found);
    if (is_byte) {
        for (int i = threadIdx.x; i < N; i += blockDim.x)
            g_mask[i] = b8[i] ? 0.0f : 1.0f;
    } else {
        const unsigned int* w32 = (const unsigned int*)resets;
        for (int i = threadIdx.x; i < N; i += blockDim.x)
            g_mask[i] = w32[i] ? 0.0f : 1.0f;
    }
}

// ===========================================================================
// fp16 conversion for A (ins) and B (Wi^T)
// ===========================================================================
__global__ void conv_ab_kernel(const float* __restrict__ ins,
                               const float* __restrict__ Wi)
{
    const size_t totalA = (size_t)T_ * B_ * D_ / 8;
    const size_t totalB = (size_t)H3_ * (D_ / 8);
    const size_t total = totalA + totalB;
    for (size_t i = (size_t)blockIdx.x * blockDim.x + threadIdx.x;
         i < total; i += (size_t)gridDim.x * blockDim.x) {
        if (i < totalA) {
            size_t base = i * 8;
            float4 a = *(const float4*)(ins + base);
            float4 b = *(const float4*)(ins + base + 4);
            *(ull*)&g_ah[base] = cvt4h(a);
            *(ull*)&g_ah[base + 4] = cvt4h(b);
        } else {
            size_t j = i - totalA;
            int n = (int)(j % H3_);
            int k8 = (int)(j / H3_) * 8;
            float4 a, b;
            a.x = Wi[(size_t)(k8+0)*H3_ + n]; a.y = Wi[(size_t)(k8+1)*H3_ + n];
            a.z = Wi[(size_t)(k8+2)*H3_ + n]; a.w = Wi[(size_t)(k8+3)*H3_ + n];
            b.x = Wi[(size_t)(k8+4)*H3_ + n]; b.y = Wi[(size_t)(k8+5)*H3_ + n];
            b.z = Wi[(size_t)(k8+6)*H3_ + n]; b.w = Wi[(size_t)(k8+7)*H3_ + n];
            size_t o = (size_t)n * D_ + k8;
            *(ull*)&g_bh[o] = cvt4h(a);
            *(ull*)&g_bh[o + 4] = cvt4h(b);
        }
    }
}

// ===========================================================================
// gi GEMM (unchanged — proven)
// ===========================================================================
#define SAK 40

__global__ __launch_bounds__(256)
void gi_gemm_kernel(const float* __restrict__ bias, float* __restrict__ C)
{
    __shared__ __half sAh[128 * SAK];
    __shared__ __half sBh[128 * SAK];

    const int tid = threadIdx.x;
    const int n0  = blockIdx.x * 128;
    const int m0  = blockIdx.y * 128;
    const int wid = tid >> 5, lane = tid & 31;
    const int wm = (wid & 1) * 64;
    const int wn = (wid >> 1) * 32;
    const int g  = lane >> 2;
    const int tg = lane & 3;

    const int sr = tid >> 1, sk = (tid & 1) * 16;
    const __half* pAh = g_ah + (size_t)(m0 + sr) * D_ + sk;
    const __half* pBh = g_bh + (size_t)(n0 + sr) * D_ + sk;

    const uint32_t aH = smem_u32(sAh) + (((wm + (lane & 15)) * SAK) +
                        ((lane & 16) ? 8 : 0)) * 2;
    const uint32_t bH = smem_u32(sBh) + (((wn + (lane & 7) +
                        ((lane & 16) ? 8 : 0)) * SAK) +
                        ((lane & 8) ? 8 : 0)) * 2;
    const int mstep = 16 * SAK * 2;
    const int nstep = 16 * SAK * 2;

    float acc[4][4][4];
    #pragma unroll
    for (int i = 0; i < 4; i++)
        #pragma unroll
        for (int j = 0; j < 4; j++)
            #pragma unroll
            for (int q = 0; q < 4; q++) acc[i][j][q] = 0.0f;

    uint4 rah0, rah1, rbh0, rbh1;
    rah0 = *(const uint4*)(pAh);     rah1 = *(const uint4*)(pAh + 8);
    rbh0 = *(const uint4*)(pBh);     rbh1 = *(const uint4*)(pBh + 8);

    for (int kc = 0; kc < D_ / 32; kc++) {
        __syncthreads();
        *(uint4*)&sAh[sr * SAK + sk] = rah0;  *(uint4*)&sAh[sr * SAK + sk + 8] = rah1;
        *(uint4*)&sBh[sr * SAK + sk] = rbh0;  *(uint4*)&sBh[sr * SAK + sk + 8] = rbh1;
        __syncthreads();

        if (kc + 1 < D_ / 32) {
            int k0 = (kc + 1) * 32;
            rah0 = *(const uint4*)(pAh + k0);  rah1 = *(const uint4*)(pAh + k0 + 8);
            rbh0 = *(const uint4*)(pBh + k0);  rbh1 = *(const uint4*)(pBh + k0 + 8);
        }

        #pragma unroll
        for (int ks = 0; ks < 2; ks++) {
            const int k2 = ks * 32;
            unsigned bh01[4], bh23[4];
            LDSM4(bh01, bH + k2);
            LDSM4(bh23, bH + nstep + k2);
            #pragma unroll
            for (int mi = 0; mi < 4; mi++) {
                unsigned ah[4];
                LDSM4(ah, aH + mi * mstep + k2);
                mma4(acc[mi][0], ah, bh01[0], bh01[1]);
                mma4(acc[mi][1], ah, bh01[2], bh01[3]);
                mma4(acc[mi][2], ah, bh23[0], bh23[1]);
                mma4(acc[mi][3], ah, bh23[2], bh23[3]);
            }
        }
    }

    #pragma unroll
    for (int ni = 0; ni < 4; ni++) {
        int col = n0 + wn + ni * 8 + tg * 2;
        float b0 = bias[col], b1 = bias[col + 1];
        #pragma unroll
        for (int mi = 0; mi < 4; mi++) {
            int row = m0 + wm + mi * 16 + g;
            float2 o0 = make_float2(acc[mi][ni][0] + b0, acc[mi][ni][1] + b1);
            float2 o1 = make_float2(acc[mi][ni][2] + b0, acc[mi][ni][3] + b1);
            *(float2*)(C + (size_t)row * H3_ + col) = o0;
            *(float2*)(C + (size_t)(row + 8) * H3_ + col) = o1;
        }
    }
}

// ===========================================================================
// Persistent GRU scan v11: per-thread targeted flag polls + double-buffered
// hs + pair-scoped gred barrier + kh0-scoped release. 1 block barrier/step.
// 512 thr = 16 warps = 2m x 4n(gate-aligned) x 2 k-halves. Mask in epilogue.
// ===========================================================================
#define WKS  520
#define HKS2 520                          // hs row stride (halves) = 1040 B
#define HSB  33280                        // one hs buffer: 32*520*2
#define OFF_HS   99840                    // W: 96*520*2
#define OFF_GRED (OFF_HS + 2*HSB)         // 99840 + 66560 = 166400
#define SCAN_SMEM (OFF_GRED + 12288)      // 178688 bytes

__global__ __launch_bounds__(SNTHR, 1)
void gru_scan_kernel(const float* __restrict__ rnn_state,
                     const float* __restrict__ Whrz,
                     const float* __restrict__ Whn,
                     const float* __restrict__ bhn,
                     const float* __restrict__ gi,
                     float* __restrict__ ys)
{
    extern __shared__ char smraw[];
    __half* Whi  = (__half*)smraw;
    float*  gred = (float*)(smraw + OFF_GRED);

    const int tid = threadIdx.x;
    const int bid = blockIdx.x;
    const int hti = bid & 15, bti = bid >> 4;
    const int hb  = hti * 32;
    const int b0  = bti * 32;

    const int wid = tid >> 5, lane = tid & 31;
    const int kh  = wid >> 3;                // k half
    const int w7  = wid & 7;
    const int wm  = (w7 & 1) * 16;           // m offset
    const int nidx = w7 >> 1;                // h strip (8 cols)
    const int g   = lane >> 2;
    const int tg  = lane & 3;

    // loader slot: row = tid>>4 (0..31), 32 halves at col (tid&15)*32
    // column range [ccol, ccol+32) is produced by tile (tid&15) exactly.
    const int crow = tid >> 4;
    const int cti  = tid & 15;               // producer tile for my columns
    const int ccol = cti * 32;

    const uint32_t smb = smem_u32(smraw);

    // ldmatrix bases: gate-aligned W strips (row = gate*32 + nidx*8 + r)
    const uint32_t wH01 = smb + ((((lane & 16) ? 32 : 0) + nidx * 8 + (lane & 7)) * WKS
                          + ((lane & 8) ? 8 : 0)) * 2;
    const uint32_t wH2  = smb + ((64 + nidx * 8 + (lane & 7)) * WKS
                          + ((lane & 8) ? 8 : 0)) * 2;
    const uint32_t hLane = (((wm + (lane & 15)) * HKS2) + ((lane & 16) ? 8 : 0)) * 2;

    // ---- one-time: W slice -> fp16 resident [96][WKS]
    for (int i = tid; i < 96 * 128; i += SNTHR) {
        int n = i >> 7, kq = (i & 127) * 4;
        int gate = n >> 5, hcol = hb + (n & 31);
        const float* src;
        int stride;
        if (gate == 0)      { src = Whrz + hcol;      stride = H2_; }
        else if (gate == 1) { src = Whrz + H_ + hcol; stride = H2_; }
        else                { src = Whn + hcol;       stride = H_;  }
        float4 v;
        v.x = src[(size_t)(kq + 0) * stride];
        v.y = src[(size_t)(kq + 1) * stride];
        v.z = src[(size_t)(kq + 2) * stride];
        v.w = src[(size_t)(kq + 3) * stride];
        *(ull*)&Whi[n * WKS + kq] = cvt4h(v);
    }

    // epilogue constants + h_old registers (kh0 threads own the outputs)
    const int eh2 = hb + nidx * 8 + tg * 2;
    const float2 bh2 = *(const float2*)(bhn + eh2);
    float2 prev0 = *(const float2*)(rnn_state + (size_t)(b0 + wm + g) * H_ + eh2);
    float2 prev1 = *(const float2*)(rnn_state + (size_t)(b0 + wm + g + 8) * H_ + eh2);
    __syncthreads();

    const unsigned* pollflag = &g_flag[(bti * 16 + cti) * 32];
    unsigned* myflag = &g_flag[(bti * 16 + hti) * 32];

    for (int t = 0; t < T_; t++) {
        // independent prefetches (before any wait)
        float2 ir0, iz0, in0, ir1, iz1, in1;
        float me0 = 0.f, me1 = 0.f;
        if (kh == 0) {
            const float* gp0 = gi + ((size_t)t * B_ + b0 + wm + g) * H3_ + eh2;
            const float* gp1 = gp0 + (size_t)8 * H3_;
            ir0 = __ldcg((const float2*)(gp0));
            iz0 = __ldcg((const float2*)(gp0 + H_));
            in0 = __ldcg((const float2*)(gp0 + 2 * H_));
            ir1 = __ldcg((const float2*)(gp1));
            iz1 = __ldcg((const float2*)(gp1 + H_));
            in1 = __ldcg((const float2*)(gp1 + 2 * H_));
            me0 = __ldg(&g_mask[t * B_ + b0 + wm + g]);
            me1 = __ldg(&g_mask[t * B_ + b0 + wm + g + 8]);
        }

        const uint32_t hbuf = smb + OFF_HS + (t & 1) * HSB;

        // ---- per-thread targeted wait + h-column load (no barrier between)
        if (t == 0) {
            __half* hs = (__half*)(smraw + OFF_HS);
            const float* src = rnn_state + (size_t)(b0 + crow) * H_ + ccol;
            #pragma unroll
            for (int q = 0; q < 2; q++) {
                float4 f0 = __ldcg((const float4*)(src + q * 16));
                float4 f1 = __ldcg((const float4*)(src + q * 16 + 4));
                float4 f2 = __ldcg((const float4*)(src + q * 16 + 8));
                float4 f3 = __ldcg((const float4*)(src + q * 16 + 12));
                *(ull*)&hs[crow * HKS2 + ccol + q * 16]      = cvt4h(f0);
                *(ull*)&hs[crow * HKS2 + ccol + q * 16 + 4]  = cvt4h(f1);
                *(ull*)&hs[crow * HKS2 + ccol + q * 16 + 8]  = cvt4h(f2);
                *(ull*)&hs[crow * HKS2 + ccol + q * 16 + 12] = cvt4h(f3);
            }
        } else {
            while (ld_acq(pollflag) < (unsigned)t) { __nanosleep(20); }
            const __half* src = g_hs + ((size_t)(t - 1) * B_ + b0 + crow) * H_ + ccol;
            const uint32_t dst = hbuf + (crow * HKS2 + ccol) * 2;
            CP_ASYNC16(dst,      src);
            CP_ASYNC16(dst + 16, src + 8);
            CP_ASYNC16(dst + 32, src + 16);
            CP_ASYNC16(dst + 48, src + 24);
            CP_COMMIT();
            CP_WAIT0();
        }
        __syncthreads();                     // hs(t) ready for all warps

        // ---- mma: this warp's k half (256 k)
        float acc[3][4];
        #pragma unroll
        for (int ni = 0; ni < 3; ni++)
            #pragma unroll
            for (int q = 0; q < 4; q++) acc[ni][q] = 0.0f;

        const uint32_t hA = hbuf + hLane;
        #pragma unroll
        for (int ks = 0; ks < 16; ks++) {
            const int kw2 = (kh * 256 + ks * 16) * 2;
            unsigned wh01[4], wh2[2], ah[4];
            LDSM4(wh01, wH01 + kw2);
            LDSM2(wh2,  wH2 + kw2);
            LDSM4(ah,   hA + kw2);
            mma4(acc[0], ah, wh01[0], wh01[1]);
            mma4(acc[1], ah, wh01[2], wh01[3]);
            mma4(acc[2], ah, wh2[0], wh2[1]);
        }

        // ---- pair-scoped k reduction: kh1 -> gred -> kh0 (named bar, 64 thr)
        float* gp = &gred[(w7 * 32 + lane) * 12];
        if (kh == 1) {
            #pragma unroll
            for (int ni = 0; ni < 3; ni++)
                #pragma unroll
                for (int q = 0; q < 4; q++) gp[ni * 4 + q] = acc[ni][q];
        }
        asm volatile("bar.sync %0, 64;" :: "r"(1 + w7) : "memory");

        if (kh == 0) {
            #pragma unroll
            for (int ni = 0; ni < 3; ni++)
                #pragma unroll
                for (int q = 0; q < 4; q++) acc[ni][q] += gp[ni * 4 + q];

            #pragma unroll
            for (int mrow = 0; mrow < 2; mrow++) {
                const int b = b0 + wm + g + 8 * mrow;
                const float me = mrow ? me1 : me0;
                const float2 pv = mrow ? prev1 : prev0;
                const float2 ir = mrow ? ir1 : ir0;
                const float2 iz = mrow ? iz1 : iz0;
                const float2 in_ = mrow ? in1 : in0;
                const int q0 = mrow * 2;

                float hm0 = pv.x * me, hm1 = pv.y * me;
                float r0 = 1.0f / (1.0f + __expf(-(ir.x + me * acc[0][q0])));
                float r1 = 1.0f / (1.0f + __expf(-(ir.y + me * acc[0][q0 + 1])));
                float z0 = 1.0f / (1.0f + __expf(-(iz.x + me * acc[1][q0])));
                float z1 = 1.0f / (1.0f + __expf(-(iz.y + me * acc[1][q0 + 1])));
                float e0 = __expf(2.0f * (in_.x + r0 * (me * acc[2][q0] + bh2.x)));
                float e1 = __expf(2.0f * (in_.y + r1 * (me * acc[2][q0 + 1] + bh2.y)));
                float n0 = __fdividef(e0 - 1.0f, e0 + 1.0f);
                float n1 = __fdividef(e1 - 1.0f, e1 + 1.0f);

                float2 out;
                out.x = (1.0f - z0) * n0 + z0 * hm0;
                out.y = (1.0f - z1) * n1 + z1 * hm1;
                *(float2*)(ys + ((size_t)t * B_ + b) * H_ + eh2) = out;
                __half2 oh = __floats2half2_rn(out.x, out.y);
                *(__half2*)(g_hs + ((size_t)t * B_ + b) * H_ + eh2) = oh;
                if (mrow) prev1 = out; else prev0 = out;
            }

            // ---- kh0-scoped release (8 warps, named bar 9)
            __threadfence();
            asm volatile("bar.sync 9, 256;" ::: "memory");
            if (tid == 0) {
                asm volatile("st.release.gpu.u32 [%0], %1;"
                             :: "l"(myflag), "r"((unsigned)(t + 1)) : "memory");
            }
        }
    }
}

// ===========================================================================
extern "C" void kernel_launch(void* const* d_in, const int* in_sizes, int n_in,
                              void* d_out, int out_size)
{
    const float* rnn_state = (const float*)d_in[0];
    const float* ins       = (const float*)d_in[1];
    const void*  resets    = d_in[2];
    const float* Wi        = (const float*)d_in[3];
    const float* bi        = (const float*)d_in[4];
    const float* Whrz      = (const float*)d_in[5];
    const float* Whn       = (const float*)d_in[6];
    const float* bhn       = (const float*)d_in[7];

    float* final_h = (float*)d_out;
    float* ys      = (float*)d_out + (size_t)B_ * H_;

    float* gi_ptr = nullptr;
    cudaGetSymbolAddress((void**)&gi_ptr, g_gi);

    cudaFuncSetAttribute(gru_scan_kernel,
                         cudaFuncAttributeMaxDynamicSharedMemorySize, SCAN_SMEM);

    prep_mask_kernel<<<1, 1024>>>(resets);               // launch #3
    conv_ab_kernel<<<2048, 256>>>(ins, Wi);              // launch #4
    gi_gemm_kernel<<<dim3(H3_ / 128, (T_ * B_) / 128), 256>>>(bi, gi_ptr);  // #5
    gru_scan_kernel<<<NBLK, SNTHR, SCAN_SMEM>>>(rnn_state, Whrz, Whn, bhn,
                                                gi_ptr, ys);                // #6
    cudaMemcpyAsync(final_h, ys + (size_t)(T_ - 1) * B_ * H_,
                    (size_t)B_ * H_ * sizeof(float),
                    cudaMemcpyDeviceToDevice, 0);
}